// round 5
// baseline (speedup 1.0000x reference)
#include <cuda_runtime.h>

#define F 256
#define F4 (F / 4)                   // 64 float4 per row
#define TOTAL_ROWS (32 * 4096)       // B*T = 131072
#define TOTAL4 ((size_t)TOTAL_ROWS * F4)   // 8,388,608 float4
#define STATS_BLOCKS 4096
#define STATS_THREADS 256
#define STATS_PER_THREAD 8           // 4096*256*8 = 8,388,608 exactly
#define EPS 1e-5f

// Scratch (no cudaMalloc allowed). Zero-initialized at module load;
// finalize_kernel restores zeros after consuming them, so every call /
// graph replay starts from a clean state without an init launch.
__device__ float g_sum[F];
__device__ float g_sumsq[F];
__device__ float g_count;            // = 64 * (#masked rows), exact in fp32
__device__ float g_scale[F];
__device__ float g_bias[F];

// ---------------------------------------------------------------------------
// Kernel 1: per-feature sum / sumsq. Unconditional streaming read of x
// weighted by w = (mask>0). STRAIGHT-LINE body: 8 independent LDG.128 + 8
// mask LDGs, no loop, so ptxas front-batches all loads (high MLP) instead of
// interleaving load->use at 32 regs (the R4 failure). Big grid (4096 blocks,
// ~7 waves) matches the memory pattern that demonstrably hits 4.6+ TB/s.
// Block covers 2048 consecutive float4 = 32 rows; thread's feature column
// f4 = tid & 63 is invariant across the 8 items (stride 256 ≡ 0 mod 64).
// ---------------------------------------------------------------------------
__global__ void __launch_bounds__(STATS_THREADS, 4)
stats_kernel(const float* __restrict__ x, const int* __restrict__ mask) {
    const int tid = threadIdx.x;
    const size_t base = (size_t)blockIdx.x * (STATS_THREADS * STATS_PER_THREAD) + tid;

    const float4* __restrict__ x4 = (const float4*)x;

    float4 v[STATS_PER_THREAD];
    float  w[STATS_PER_THREAD];
#pragma unroll
    for (int k = 0; k < STATS_PER_THREAD; ++k) {
        const size_t i = base + (size_t)k * STATS_THREADS;
        w[k] = (mask[i >> 6] > 0) ? 1.0f : 0.0f;   // warp-broadcast L1 hit
        v[k] = __ldcs(&x4[i]);                     // streaming 16B load
    }

    float4 acc  = make_float4(0.f, 0.f, 0.f, 0.f);
    float4 acc2 = make_float4(0.f, 0.f, 0.f, 0.f);
    float  cntf = 0.f;
#pragma unroll
    for (int k = 0; k < STATS_PER_THREAD; ++k) {
        const float wx = w[k];
        acc.x  = fmaf(v[k].x, wx, acc.x);
        acc.y  = fmaf(v[k].y, wx, acc.y);
        acc.z  = fmaf(v[k].z, wx, acc.z);
        acc.w  = fmaf(v[k].w, wx, acc.w);
        acc2.x = fmaf(v[k].x * wx, v[k].x, acc2.x);
        acc2.y = fmaf(v[k].y * wx, v[k].y, acc2.y);
        acc2.z = fmaf(v[k].z * wx, v[k].z, acc2.z);
        acc2.w = fmaf(v[k].w * wx, v[k].w, acc2.w);
        cntf  += wx;
    }

    // ---- intra-block reduction: 4 row-slots -> 1, then atomics ----
    const int f4  = tid & 63;
    const int sub = tid >> 6;

    __shared__ float4 s_sum[256];
    __shared__ float4 s_sq[256];
    __shared__ float  s_c[256];
    s_sum[tid] = acc;
    s_sq[tid]  = acc2;
    s_c[tid]   = cntf;
    __syncthreads();

    if (sub == 0) {
#pragma unroll
        for (int k = 1; k < 4; k++) {
            float4 a = s_sum[tid + 64 * k];
            float4 b = s_sq[tid + 64 * k];
            acc.x += a.x; acc.y += a.y; acc.z += a.z; acc.w += a.w;
            acc2.x += b.x; acc2.y += b.y; acc2.z += b.z; acc2.w += b.w;
            cntf += s_c[tid + 64 * k];
        }
        const int fb = f4 * 4;
        atomicAdd(&g_sum[fb + 0], acc.x);
        atomicAdd(&g_sum[fb + 1], acc.y);
        atomicAdd(&g_sum[fb + 2], acc.z);
        atomicAdd(&g_sum[fb + 3], acc.w);
        atomicAdd(&g_sumsq[fb + 0], acc2.x);
        atomicAdd(&g_sumsq[fb + 1], acc2.y);
        atomicAdd(&g_sumsq[fb + 2], acc2.z);
        atomicAdd(&g_sumsq[fb + 3], acc2.w);

        // one count atomic per block: reduce 64 -> 1 with shuffles
        float c = cntf;
#pragma unroll
        for (int o = 16; o > 0; o >>= 1)
            c += __shfl_down_sync(0xffffffffu, c, o);
        if ((tid & 31) == 0) s_c[tid] = c;   // lanes 0 of warps 0,1
    }
    __syncthreads();
    if (tid == 0) atomicAdd(&g_count, s_c[0] + s_c[32]);
}

// ---------------------------------------------------------------------------
// Kernel 2: finalize — fold mean/var/gamma/beta into per-feature affine,
// then RESET the accumulators so the next call/replay starts clean.
// ---------------------------------------------------------------------------
__global__ void finalize_kernel(const float* __restrict__ gamma,
                                const float* __restrict__ beta) {
    int f = threadIdx.x;
    float cnt  = g_count * (1.0f / 64.0f);   // each masked row counted by 64 threads
    float mean = g_sum[f] / cnt;
    float var  = g_sumsq[f] / cnt - mean * mean;
    float s    = rsqrtf(var + EPS) * gamma[f];
    g_scale[f] = s;
    g_bias[f]  = beta[f] - mean * s;
    // restore zero-state invariant
    g_sum[f]   = 0.f;
    g_sumsq[f] = 0.f;
    if (f == 0) g_count = 0.f;
}

// ---------------------------------------------------------------------------
// Kernel 3: apply. float4-vectorized; mask branch warp-uniform. Streaming
// hints on the 256 MB of bulk traffic. (~90% of mixed HBM floor.)
// ---------------------------------------------------------------------------
__global__ void __launch_bounds__(256) apply_kernel(const float* __restrict__ x,
                                                    const int*   __restrict__ mask,
                                                    float*       __restrict__ out) {
    const size_t i = (size_t)blockIdx.x * blockDim.x + threadIdx.x;  // float4 index
    const float4* __restrict__ x4 = (const float4*)x;
    float4* __restrict__ out4 = (float4*)out;

    const int row = (int)(i >> 6);       // 64 float4 per row
    const int f4  = (int)(i & 63);

    float4 v = __ldcs(&x4[i]);
    if (mask[row] > 0) {
        const float4* s4 = (const float4*)g_scale;
        const float4* b4 = (const float4*)g_bias;
        float4 s = s4[f4];
        float4 b = b4[f4];
        v.x = fmaf(v.x, s.x, b.x);
        v.y = fmaf(v.y, s.y, b.y);
        v.z = fmaf(v.z, s.z, b.z);
        v.w = fmaf(v.w, s.w, b.w);
    }
    __stcs(&out4[i], v);
}

// ---------------------------------------------------------------------------
extern "C" void kernel_launch(void* const* d_in, const int* in_sizes, int n_in,
                              void* d_out, int out_size) {
    const float* x     = (const float*)d_in[0];
    const int*   mask  = (const int*)d_in[1];
    const float* gamma = (const float*)d_in[2];
    const float* beta  = (const float*)d_in[3];
    float*       out   = (float*)d_out;

    stats_kernel<<<STATS_BLOCKS, STATS_THREADS>>>(x, mask);
    finalize_kernel<<<1, 256>>>(gamma, beta);
    // 32*4096*256 / 4 = 8,388,608 float4 -> 32768 blocks of 256
    apply_kernel<<<32768, 256>>>(x, mask, out);
}

// round 6
// speedup vs baseline: 2.3230x; 2.3230x over previous
#include <cuda_runtime.h>

#define F 256
#define F4 (F / 4)                   // 64 float4 per row
#define TOTAL_ROWS (32 * 4096)       // B*T = 131072
#define STATS_BLOCKS 1024
#define STATS_THREADS 256
#define PER_THREAD 32                // 1024*256*32 = 8,388,608 float4 exactly
#define EPS 1e-5f

// Per-block partials (plain stores, NO atomics). 1024 blocks x 256 floats
// each for sum and sumsq (2 MB total) + per-block count. Fully overwritten
// on every call -> deterministic, graph-replay safe, no init kernel.
__device__ float g_psum[STATS_BLOCKS * F];
__device__ float g_psq [STATS_BLOCKS * F];
__device__ float g_pcnt[STATS_BLOCKS];
__device__ float g_scale[F];
__device__ float g_bias[F];

// ---------------------------------------------------------------------------
// Kernel 1: per-feature partial sum / sumsq. Unconditional streaming read of
// x weighted by w = (mask>0) (streaming 128 MB beats masked gather). Batches
// of 8 independent LDG.128 for MLP. Block covers a contiguous 128 KB chunk;
// thread's feature column f4 = tid & 63 is invariant (stride 256 ≡ 0 mod 64).
// Epilogue: smem reduce + COALESCED PLAIN STORES of the block's partials —
// the R4/R5 killer (2 KB-region atomic serialization) is gone.
// ---------------------------------------------------------------------------
__global__ void __launch_bounds__(STATS_THREADS)
stats_kernel(const float* __restrict__ x, const int* __restrict__ mask) {
    const int tid = threadIdx.x;
    const size_t base = (size_t)blockIdx.x * (STATS_THREADS * PER_THREAD) + tid;

    const float4* __restrict__ x4 = (const float4*)x;

    float4 acc  = make_float4(0.f, 0.f, 0.f, 0.f);
    float4 acc2 = make_float4(0.f, 0.f, 0.f, 0.f);
    float  cntf = 0.f;

#pragma unroll 1
    for (int it = 0; it < PER_THREAD / 8; ++it) {
        float4 v[8];
        float  w[8];
#pragma unroll
        for (int u = 0; u < 8; ++u) {
            const size_t i = base + (size_t)(it * 8 + u) * STATS_THREADS;
            w[u] = (mask[i >> 6] > 0) ? 1.0f : 0.0f;   // warp-broadcast hit
            v[u] = __ldcs(&x4[i]);                     // streaming 16B load
        }
#pragma unroll
        for (int u = 0; u < 8; ++u) {
            const float wx = w[u];
            acc.x  = fmaf(v[u].x, wx, acc.x);
            acc.y  = fmaf(v[u].y, wx, acc.y);
            acc.z  = fmaf(v[u].z, wx, acc.z);
            acc.w  = fmaf(v[u].w, wx, acc.w);
            acc2.x = fmaf(v[u].x * wx, v[u].x, acc2.x);
            acc2.y = fmaf(v[u].y * wx, v[u].y, acc2.y);
            acc2.z = fmaf(v[u].z * wx, v[u].z, acc2.z);
            acc2.w = fmaf(v[u].w * wx, v[u].w, acc2.w);
            cntf  += wx;
        }
    }

    // ---- intra-block reduction across the 4 row-slots ----
    const int f4  = tid & 63;
    const int sub = tid >> 6;

    __shared__ float4 s_sum[256];
    __shared__ float4 s_sq[256];
    __shared__ float  s_c[256];
    s_sum[tid] = acc;
    s_sq[tid]  = acc2;
    s_c[tid]   = cntf;
    __syncthreads();

    if (sub == 0) {
#pragma unroll
        for (int k = 1; k < 4; k++) {
            float4 a = s_sum[tid + 64 * k];
            float4 b = s_sq[tid + 64 * k];
            acc.x += a.x; acc.y += a.y; acc.z += a.z; acc.w += a.w;
            acc2.x += b.x; acc2.y += b.y; acc2.z += b.z; acc2.w += b.w;
        }
        s_sum[f4] = acc;    // reduced partials -> first 64 float4 (=256 floats)
        s_sq[f4]  = acc2;
    }
    __syncthreads();

    // coalesced plain stores: thread tid writes feature tid's partial
    const float* rs = (const float*)s_sum;
    const float* rq = (const float*)s_sq;
    const size_t o = (size_t)blockIdx.x * F + tid;
    g_psum[o] = rs[tid];
    g_psq[o]  = rq[tid];

    // per-block count: 256 -> 1 via warp shuffles + tiny smem tree
    float c = s_c[tid];
#pragma unroll
    for (int off = 16; off > 0; off >>= 1)
        c += __shfl_down_sync(0xffffffffu, c, off);
    if ((tid & 31) == 0) s_c[tid >> 5] = c;
    __syncthreads();
    if (tid == 0) {
        float t = s_c[0] + s_c[1] + s_c[2] + s_c[3]
                + s_c[4] + s_c[5] + s_c[6] + s_c[7];
        g_pcnt[blockIdx.x] = t;
    }
}

// ---------------------------------------------------------------------------
// Kernel 2: reduce the 1024 per-block partials + finalize into per-feature
// affine (scale, bias). One block, 1024 threads: thread = (feature f, slice
// j of 256 stats-blocks). Reads are coalesced across f and unrolled x8 for
// MLP; the 2 MB of partials are L2-resident.
// ---------------------------------------------------------------------------
__global__ void __launch_bounds__(1024)
reduce_finalize_kernel(const float* __restrict__ gamma,
                       const float* __restrict__ beta) {
    const int tid = threadIdx.x;
    const int f = tid & 255;
    const int j = tid >> 8;          // 0..3

    float sum = 0.f, sq = 0.f;
#pragma unroll 1
    for (int b = j * 256; b < (j + 1) * 256; b += 8) {
        float a0[8], a1[8];
#pragma unroll
        for (int u = 0; u < 8; ++u) {
            a0[u] = g_psum[(size_t)(b + u) * F + f];
            a1[u] = g_psq [(size_t)(b + u) * F + f];
        }
#pragma unroll
        for (int u = 0; u < 8; ++u) { sum += a0[u]; sq += a1[u]; }
    }

    __shared__ float s_sum[1024];
    __shared__ float s_sq[1024];
    __shared__ float s_c[1024];
    __shared__ float s_total;

    s_sum[tid] = sum;
    s_sq[tid]  = sq;
    s_c[tid]   = g_pcnt[tid];        // exactly 1024 blocks, 1024 threads
    __syncthreads();

    // total count: tree-reduce 1024 -> 1
    if (tid < 512) s_c[tid] += s_c[tid + 512];
    __syncthreads();
    if (tid < 256) s_c[tid] += s_c[tid + 256];
    __syncthreads();
    if (tid < 32) {
        float c = 0.f;
#pragma unroll
        for (int k = 0; k < 8; ++k) c += s_c[tid + 32 * k];
#pragma unroll
        for (int off = 16; off > 0; off >>= 1)
            c += __shfl_down_sync(0xffffffffu, c, off);
        if (tid == 0) s_total = c;
    }
    __syncthreads();

    if (j == 0) {
        sum += s_sum[f + 256] + s_sum[f + 512] + s_sum[f + 768];
        sq  += s_sq[f + 256]  + s_sq[f + 512]  + s_sq[f + 768];
        float cnt  = s_total * (1.0f / 64.0f);   // each row counted by 64 threads
        float mean = sum / cnt;
        float var  = sq / cnt - mean * mean;
        float s    = rsqrtf(var + EPS) * gamma[f];
        g_scale[f] = s;
        g_bias[f]  = beta[f] - mean * s;
    }
}

// ---------------------------------------------------------------------------
// Kernel 3: apply. float4-vectorized; mask branch warp-uniform; streaming
// hints on the 256 MB of bulk traffic. (~84% of LTS cap — unchanged.)
// ---------------------------------------------------------------------------
__global__ void __launch_bounds__(256) apply_kernel(const float* __restrict__ x,
                                                    const int*   __restrict__ mask,
                                                    float*       __restrict__ out) {
    const size_t i = (size_t)blockIdx.x * blockDim.x + threadIdx.x;  // float4 index
    const float4* __restrict__ x4 = (const float4*)x;
    float4* __restrict__ out4 = (float4*)out;

    const int row = (int)(i >> 6);       // 64 float4 per row
    const int f4  = (int)(i & 63);

    float4 v = __ldcs(&x4[i]);
    if (mask[row] > 0) {
        const float4* s4 = (const float4*)g_scale;
        const float4* b4 = (const float4*)g_bias;
        float4 s = s4[f4];
        float4 b = b4[f4];
        v.x = fmaf(v.x, s.x, b.x);
        v.y = fmaf(v.y, s.y, b.y);
        v.z = fmaf(v.z, s.z, b.z);
        v.w = fmaf(v.w, s.w, b.w);
    }
    __stcs(&out4[i], v);
}

// ---------------------------------------------------------------------------
extern "C" void kernel_launch(void* const* d_in, const int* in_sizes, int n_in,
                              void* d_out, int out_size) {
    const float* x     = (const float*)d_in[0];
    const int*   mask  = (const int*)d_in[1];
    const float* gamma = (const float*)d_in[2];
    const float* beta  = (const float*)d_in[3];
    float*       out   = (float*)d_out;

    stats_kernel<<<STATS_BLOCKS, STATS_THREADS>>>(x, mask);
    reduce_finalize_kernel<<<1, 1024>>>(gamma, beta);
    // 32*4096*256 / 4 = 8,388,608 float4 -> 32768 blocks of 256
    apply_kernel<<<32768, 256>>>(x, mask, out);
}

// round 7
// speedup vs baseline: 2.5092x; 1.0801x over previous
#include <cuda_runtime.h>

#define F 256
#define F4 (F / 4)                   // 64 float4 per row
#define TOTAL_ROWS (32 * 4096)       // B*T = 131072
#define STATS_BLOCKS 1024
#define STATS_THREADS 256
#define PER_THREAD 32                // 1024*256*32 = 8,388,608 float4 exactly
#define RED_BLOCKS 8                 // parallel reduce: 8 blocks x 32 features
#define EPS 1e-5f

// Per-block partials (plain stores, NO atomics — the R4/R5 killer was
// 2KB-region atomic serialization). Fully overwritten every call ->
// deterministic, graph-replay safe, no init kernel.
__device__ float g_psum[STATS_BLOCKS * F];
__device__ float g_psq [STATS_BLOCKS * F];
__device__ float g_pcnt[STATS_BLOCKS];
__device__ float g_scale[F];
__device__ float g_bias[F];

// ---------------------------------------------------------------------------
// Kernel 1: per-feature partial sum / sumsq. Unconditional streaming read of
// x weighted by w = (mask>0). Batches of 8 independent LDG.128 for MLP.
// Epilogue: smem reduce + coalesced plain stores of block partials.
// (28.4 us @ 4.86 TB/s in R6 — unchanged.)
// ---------------------------------------------------------------------------
__global__ void __launch_bounds__(STATS_THREADS)
stats_kernel(const float* __restrict__ x, const int* __restrict__ mask) {
    const int tid = threadIdx.x;
    const size_t base = (size_t)blockIdx.x * (STATS_THREADS * PER_THREAD) + tid;

    const float4* __restrict__ x4 = (const float4*)x;

    float4 acc  = make_float4(0.f, 0.f, 0.f, 0.f);
    float4 acc2 = make_float4(0.f, 0.f, 0.f, 0.f);
    float  cntf = 0.f;

#pragma unroll 1
    for (int it = 0; it < PER_THREAD / 8; ++it) {
        float4 v[8];
        float  w[8];
#pragma unroll
        for (int u = 0; u < 8; ++u) {
            const size_t i = base + (size_t)(it * 8 + u) * STATS_THREADS;
            w[u] = (mask[i >> 6] > 0) ? 1.0f : 0.0f;   // warp-broadcast hit
            v[u] = __ldcs(&x4[i]);                     // streaming 16B load
        }
#pragma unroll
        for (int u = 0; u < 8; ++u) {
            const float wx = w[u];
            acc.x  = fmaf(v[u].x, wx, acc.x);
            acc.y  = fmaf(v[u].y, wx, acc.y);
            acc.z  = fmaf(v[u].z, wx, acc.z);
            acc.w  = fmaf(v[u].w, wx, acc.w);
            acc2.x = fmaf(v[u].x * wx, v[u].x, acc2.x);
            acc2.y = fmaf(v[u].y * wx, v[u].y, acc2.y);
            acc2.z = fmaf(v[u].z * wx, v[u].z, acc2.z);
            acc2.w = fmaf(v[u].w * wx, v[u].w, acc2.w);
            cntf  += wx;
        }
    }

    // ---- intra-block reduction across the 4 row-slots ----
    const int f4  = tid & 63;
    const int sub = tid >> 6;

    __shared__ float4 s_sum[256];
    __shared__ float4 s_sq[256];
    __shared__ float  s_c[256];
    s_sum[tid] = acc;
    s_sq[tid]  = acc2;
    s_c[tid]   = cntf;
    __syncthreads();

    if (sub == 0) {
#pragma unroll
        for (int k = 1; k < 4; k++) {
            float4 a = s_sum[tid + 64 * k];
            float4 b = s_sq[tid + 64 * k];
            acc.x += a.x; acc.y += a.y; acc.z += a.z; acc.w += a.w;
            acc2.x += b.x; acc2.y += b.y; acc2.z += b.z; acc2.w += b.w;
        }
        s_sum[f4] = acc;    // reduced partials -> first 64 float4 (=256 floats)
        s_sq[f4]  = acc2;
    }
    __syncthreads();

    // coalesced plain stores: thread tid writes feature tid's partial
    const float* rs = (const float*)s_sum;
    const float* rq = (const float*)s_sq;
    const size_t o = (size_t)blockIdx.x * F + tid;
    g_psum[o] = rs[tid];
    g_psq[o]  = rq[tid];

    // per-block count: 256 -> 1 via warp shuffles + tiny smem tree
    float c = s_c[tid];
#pragma unroll
    for (int off = 16; off > 0; off >>= 1)
        c += __shfl_down_sync(0xffffffffu, c, off);
    if ((tid & 31) == 0) s_c[tid >> 5] = c;
    __syncthreads();
    if (tid == 0) {
        float t = s_c[0] + s_c[1] + s_c[2] + s_c[3]
                + s_c[4] + s_c[5] + s_c[6] + s_c[7];
        g_pcnt[blockIdx.x] = t;
    }
}

// ---------------------------------------------------------------------------
// Kernel 2: parallel reduce + finalize. 8 blocks x 256 threads; block b owns
// features [b*32, b*32+32). Thread = (feature f_local = tid&31, slice
// j = tid>>5 of 128 stats-blocks). Warp reads 32 contiguous floats per
// stats-block (coalesced), unroll-8 for MLP; partials are L2-resident.
// Count (4 KB) reduced redundantly per block.
// ---------------------------------------------------------------------------
__global__ void __launch_bounds__(256)
reduce_finalize_kernel(const float* __restrict__ gamma,
                       const float* __restrict__ beta) {
    const int tid = threadIdx.x;
    const int fl  = tid & 31;                  // feature within block's slice
    const int j   = tid >> 5;                  // 0..7 (slice of stats-blocks)
    const int f   = blockIdx.x * 32 + fl;      // global feature

    float sum = 0.f, sq = 0.f;
#pragma unroll 1
    for (int b = j * 128; b < (j + 1) * 128; b += 8) {
        float a0[8], a1[8];
#pragma unroll
        for (int u = 0; u < 8; ++u) {
            a0[u] = g_psum[(size_t)(b + u) * F + f];
            a1[u] = g_psq [(size_t)(b + u) * F + f];
        }
#pragma unroll
        for (int u = 0; u < 8; ++u) { sum += a0[u]; sq += a1[u]; }
    }

    // redundant per-block total count: 1024 floats / 256 threads = 4 each
    float c = g_pcnt[tid] + g_pcnt[tid + 256] + g_pcnt[tid + 512] + g_pcnt[tid + 768];
#pragma unroll
    for (int off = 16; off > 0; off >>= 1)
        c += __shfl_down_sync(0xffffffffu, c, off);

    __shared__ float s_sum[256];
    __shared__ float s_sq[256];
    __shared__ float s_cw[8];
    __shared__ float s_total;

    s_sum[tid] = sum;
    s_sq[tid]  = sq;
    if ((tid & 31) == 0) s_cw[tid >> 5] = c;
    __syncthreads();

    if (tid < 32) {
        if (tid == 0) {
            float t = 0.f;
#pragma unroll
            for (int k = 0; k < 8; ++k) t += s_cw[k];
            s_total = t;
        }
    }
    __syncthreads();

    if (j == 0) {
#pragma unroll
        for (int k = 1; k < 8; ++k) {
            sum += s_sum[fl + 32 * k];
            sq  += s_sq[fl + 32 * k];
        }
        float cnt  = s_total * (1.0f / 64.0f);   // each row counted by 64 threads
        float mean = sum / cnt;
        float var  = sq / cnt - mean * mean;
        float s    = rsqrtf(var + EPS) * gamma[f];
        g_scale[f] = s;
        g_bias[f]  = beta[f] - mean * s;
    }
}

// ---------------------------------------------------------------------------
// Kernel 3: apply. float4-vectorized; mask branch warp-uniform; streaming
// hints. (48.6 us @ 4.68 TB/s — unchanged.)
// ---------------------------------------------------------------------------
__global__ void __launch_bounds__(256) apply_kernel(const float* __restrict__ x,
                                                    const int*   __restrict__ mask,
                                                    float*       __restrict__ out) {
    const size_t i = (size_t)blockIdx.x * blockDim.x + threadIdx.x;  // float4 index
    const float4* __restrict__ x4 = (const float4*)x;
    float4* __restrict__ out4 = (float4*)out;

    const int row = (int)(i >> 6);       // 64 float4 per row
    const int f4  = (int)(i & 63);

    float4 v = __ldcs(&x4[i]);
    if (mask[row] > 0) {
        const float4* s4 = (const float4*)g_scale;
        const float4* b4 = (const float4*)g_bias;
        float4 s = s4[f4];
        float4 b = b4[f4];
        v.x = fmaf(v.x, s.x, b.x);
        v.y = fmaf(v.y, s.y, b.y);
        v.z = fmaf(v.z, s.z, b.z);
        v.w = fmaf(v.w, s.w, b.w);
    }
    __stcs(&out4[i], v);
}

// ---------------------------------------------------------------------------
extern "C" void kernel_launch(void* const* d_in, const int* in_sizes, int n_in,
                              void* d_out, int out_size) {
    const float* x     = (const float*)d_in[0];
    const int*   mask  = (const int*)d_in[1];
    const float* gamma = (const float*)d_in[2];
    const float* beta  = (const float*)d_in[3];
    float*       out   = (float*)d_out;

    stats_kernel<<<STATS_BLOCKS, STATS_THREADS>>>(x, mask);
    reduce_finalize_kernel<<<RED_BLOCKS, 256>>>(gamma, beta);
    // 32*4096*256 / 4 = 8,388,608 float4 -> 32768 blocks of 256
    apply_kernel<<<32768, 256>>>(x, mask, out);
}

// round 8
// speedup vs baseline: 2.5533x; 1.0176x over previous
#include <cuda_runtime.h>

#define F 256
#define F4 (F / 4)                   // 64 float4 per row
#define TOTAL_ROWS (32 * 4096)       // B*T = 131072
#define STATS_BLOCKS 1024
#define STATS_THREADS 256
#define PER_THREAD 32                // 1024*256*32 = 8,388,608 float4 exactly
#define RED_BLOCKS 8                 // parallel reduce: 8 blocks x 32 features
#define APPLY_BLOCKS 32768
#define EPS 1e-5f

// Per-block partials (plain stores, NO atomics — the R4/R5 killer was
// 2KB-region atomic serialization). Fully overwritten every call ->
// deterministic, graph-replay safe, no init kernel.
__device__ float g_psum[STATS_BLOCKS * F];
__device__ float g_psq [STATS_BLOCKS * F];
__device__ float g_pcnt[STATS_BLOCKS];
__device__ float g_scale[F];
__device__ float g_bias[F];

// ---------------------------------------------------------------------------
// Kernel 1: per-feature partial sum / sumsq. Unconditional streaming read of
// x weighted by w = (mask>0). Batches of 8 independent LDG.128 for MLP.
// __ldcg (NOT __ldcs): deliberately FILL L2 with x so the apply pass can
// re-read the resident tail instead of going to DRAM (L2 ~126MB vs x 128MB).
// ---------------------------------------------------------------------------
__global__ void __launch_bounds__(STATS_THREADS)
stats_kernel(const float* __restrict__ x, const int* __restrict__ mask) {
    const int tid = threadIdx.x;
    const size_t base = (size_t)blockIdx.x * (STATS_THREADS * PER_THREAD) + tid;

    const float4* __restrict__ x4 = (const float4*)x;

    float4 acc  = make_float4(0.f, 0.f, 0.f, 0.f);
    float4 acc2 = make_float4(0.f, 0.f, 0.f, 0.f);
    float  cntf = 0.f;

#pragma unroll 1
    for (int it = 0; it < PER_THREAD / 8; ++it) {
        float4 v[8];
        float  w[8];
#pragma unroll
        for (int u = 0; u < 8; ++u) {
            const size_t i = base + (size_t)(it * 8 + u) * STATS_THREADS;
            w[u] = (mask[i >> 6] > 0) ? 1.0f : 0.0f;   // warp-broadcast hit
            v[u] = __ldcg(&x4[i]);                     // fill L2 (reuse in apply)
        }
#pragma unroll
        for (int u = 0; u < 8; ++u) {
            const float wx = w[u];
            acc.x  = fmaf(v[u].x, wx, acc.x);
            acc.y  = fmaf(v[u].y, wx, acc.y);
            acc.z  = fmaf(v[u].z, wx, acc.z);
            acc.w  = fmaf(v[u].w, wx, acc.w);
            acc2.x = fmaf(v[u].x * wx, v[u].x, acc2.x);
            acc2.y = fmaf(v[u].y * wx, v[u].y, acc2.y);
            acc2.z = fmaf(v[u].z * wx, v[u].z, acc2.z);
            acc2.w = fmaf(v[u].w * wx, v[u].w, acc2.w);
            cntf  += wx;
        }
    }

    // ---- intra-block reduction across the 4 row-slots ----
    const int f4  = tid & 63;
    const int sub = tid >> 6;

    __shared__ float4 s_sum[256];
    __shared__ float4 s_sq[256];
    __shared__ float  s_c[256];
    s_sum[tid] = acc;
    s_sq[tid]  = acc2;
    s_c[tid]   = cntf;
    __syncthreads();

    if (sub == 0) {
#pragma unroll
        for (int k = 1; k < 4; k++) {
            float4 a = s_sum[tid + 64 * k];
            float4 b = s_sq[tid + 64 * k];
            acc.x += a.x; acc.y += a.y; acc.z += a.z; acc.w += a.w;
            acc2.x += b.x; acc2.y += b.y; acc2.z += b.z; acc2.w += b.w;
        }
        s_sum[f4] = acc;    // reduced partials -> first 64 float4 (=256 floats)
        s_sq[f4]  = acc2;
    }
    __syncthreads();

    // coalesced plain stores: thread tid writes feature tid's partial
    const float* rs = (const float*)s_sum;
    const float* rq = (const float*)s_sq;
    const size_t o = (size_t)blockIdx.x * F + tid;
    g_psum[o] = rs[tid];
    g_psq[o]  = rq[tid];

    // per-block count: 256 -> 1 via warp shuffles + tiny smem tree
    float c = s_c[tid];
#pragma unroll
    for (int off = 16; off > 0; off >>= 1)
        c += __shfl_down_sync(0xffffffffu, c, off);
    if ((tid & 31) == 0) s_c[tid >> 5] = c;
    __syncthreads();
    if (tid == 0) {
        float t = s_c[0] + s_c[1] + s_c[2] + s_c[3]
                + s_c[4] + s_c[5] + s_c[6] + s_c[7];
        g_pcnt[blockIdx.x] = t;
    }
}

// ---------------------------------------------------------------------------
// Kernel 2: parallel reduce + finalize. 8 blocks x 256 threads; block b owns
// features [b*32, b*32+32). Thread = (feature fl = tid&31, slice j = tid>>5
// of 128 stats-blocks). Coalesced, unroll-8; partials are L2-resident.
// ---------------------------------------------------------------------------
__global__ void __launch_bounds__(256)
reduce_finalize_kernel(const float* __restrict__ gamma,
                       const float* __restrict__ beta) {
    const int tid = threadIdx.x;
    const int fl  = tid & 31;                  // feature within block's slice
    const int j   = tid >> 5;                  // 0..7 (slice of stats-blocks)
    const int f   = blockIdx.x * 32 + fl;      // global feature

    float sum = 0.f, sq = 0.f;
#pragma unroll 1
    for (int b = j * 128; b < (j + 1) * 128; b += 8) {
        float a0[8], a1[8];
#pragma unroll
        for (int u = 0; u < 8; ++u) {
            a0[u] = g_psum[(size_t)(b + u) * F + f];
            a1[u] = g_psq [(size_t)(b + u) * F + f];
        }
#pragma unroll
        for (int u = 0; u < 8; ++u) { sum += a0[u]; sq += a1[u]; }
    }

    // redundant per-block total count: 1024 floats / 256 threads = 4 each
    float c = g_pcnt[tid] + g_pcnt[tid + 256] + g_pcnt[tid + 512] + g_pcnt[tid + 768];
#pragma unroll
    for (int off = 16; off > 0; off >>= 1)
        c += __shfl_down_sync(0xffffffffu, c, off);

    __shared__ float s_sum[256];
    __shared__ float s_sq[256];
    __shared__ float s_cw[8];
    __shared__ float s_total;

    s_sum[tid] = sum;
    s_sq[tid]  = sq;
    if ((tid & 31) == 0) s_cw[tid >> 5] = c;
    __syncthreads();

    if (tid == 0) {
        float t = 0.f;
#pragma unroll
        for (int k = 0; k < 8; ++k) t += s_cw[k];
        s_total = t;
    }
    __syncthreads();

    if (j == 0) {
#pragma unroll
        for (int k = 1; k < 8; ++k) {
            sum += s_sum[fl + 32 * k];
            sq  += s_sq[fl + 32 * k];
        }
        float cnt  = s_total * (1.0f / 64.0f);   // each row counted by 64 threads
        float mean = sum / cnt;
        float var  = sq / cnt - mean * mean;
        float s    = rsqrtf(var + EPS) * gamma[f];
        g_scale[f] = s;
        g_bias[f]  = beta[f] - mean * s;
    }
}

// ---------------------------------------------------------------------------
// Kernel 3: apply, REVERSED block order. Stats just streamed x through L2
// with __ldcg, so the HIGH addresses of x are L2-resident (LRU tail).
// First-scheduled apply blocks (low blockIdx) take the highest chunk and
// consume it while still resident. Within-block layout unchanged -> fully
// coalesced. x reads evict-first (__ldcs, no further reuse); out stores
// streaming (__stcs) to limit write-allocate pollution of resident x lines.
// ---------------------------------------------------------------------------
__global__ void __launch_bounds__(256) apply_kernel(const float* __restrict__ x,
                                                    const int*   __restrict__ mask,
                                                    float*       __restrict__ out) {
    const unsigned bid = (unsigned)(APPLY_BLOCKS - 1) - blockIdx.x;  // reverse
    const size_t i = (size_t)bid * blockDim.x + threadIdx.x;         // float4 index
    const float4* __restrict__ x4 = (const float4*)x;
    float4* __restrict__ out4 = (float4*)out;

    const int row = (int)(i >> 6);       // 64 float4 per row
    const int f4  = (int)(i & 63);

    float4 v = __ldcs(&x4[i]);
    if (mask[row] > 0) {
        const float4* s4 = (const float4*)g_scale;
        const float4* b4 = (const float4*)g_bias;
        float4 s = s4[f4];
        float4 b = b4[f4];
        v.x = fmaf(v.x, s.x, b.x);
        v.y = fmaf(v.y, s.y, b.y);
        v.z = fmaf(v.z, s.z, b.z);
        v.w = fmaf(v.w, s.w, b.w);
    }
    __stcs(&out4[i], v);
}

// ---------------------------------------------------------------------------
extern "C" void kernel_launch(void* const* d_in, const int* in_sizes, int n_in,
                              void* d_out, int out_size) {
    const float* x     = (const float*)d_in[0];
    const int*   mask  = (const int*)d_in[1];
    const float* gamma = (const float*)d_in[2];
    const float* beta  = (const float*)d_in[3];
    float*       out   = (float*)d_out;

    stats_kernel<<<STATS_BLOCKS, STATS_THREADS>>>(x, mask);
    reduce_finalize_kernel<<<RED_BLOCKS, 256>>>(gamma, beta);
    // 32*4096*256 / 4 = 8,388,608 float4 -> 32768 blocks of 256
    apply_kernel<<<APPLY_BLOCKS, 256>>>(x, mask, out);
}

// round 9
// speedup vs baseline: 2.8815x; 1.1286x over previous
#include <cuda_runtime.h>

#define F 256
#define F4 (F / 4)                   // 64 float4 per row
#define TOTAL_ROWS (32 * 4096)       // B*T = 131072
#define STATS_BLOCKS 1024
#define STATS_THREADS 256
#define RED_BLOCKS 8
#define APPLY_BLOCKS 32768
#define COMPACT_BLOCKS (TOTAL_ROWS / 1024)   // 128 blocks x 256 thr x 4 rows
#define EPS 1e-5f

// Scratch (no cudaMalloc). g_ctr is zero at load; apply_kernel resets it at
// the END of every call, so each call/replay starts from 0. Everything else
// is fully overwritten before being read -> deterministic, graph-safe.
__device__ unsigned g_ctr;                    // number of masked rows
__device__ int      g_rows[TOTAL_ROWS];       // compacted masked-row indices
__device__ float    g_psum[STATS_BLOCKS * F];
__device__ float    g_psq [STATS_BLOCKS * F];
__device__ float    g_scale[F];
__device__ float    g_bias[F];

// ---------------------------------------------------------------------------
// Kernel 0: compact masked row indices. Each thread scans 4 mask entries
// (int4); warp scan + block scan + one atomicAdd per block for the base.
// 512 KB read / ~256 KB write -> ~2-3 us.
// ---------------------------------------------------------------------------
__global__ void __launch_bounds__(256) compact_kernel(const int* __restrict__ mask) {
    const int tid = threadIdx.x;
    const int gi  = blockIdx.x * 256 + tid;          // int4 index
    int4 m = ((const int4*)mask)[gi];
    const int c0 = m.x > 0, c1 = m.y > 0, c2 = m.z > 0, c3 = m.w > 0;
    const int cnt = c0 + c1 + c2 + c3;

    // warp inclusive scan of cnt
    const int lane = tid & 31, wid = tid >> 5;
    int incl = cnt;
#pragma unroll
    for (int off = 1; off < 32; off <<= 1) {
        int t = __shfl_up_sync(0xffffffffu, incl, off);
        if (lane >= off) incl += t;
    }

    __shared__ int wsum[8];
    __shared__ int sbase;
    if (lane == 31) wsum[wid] = incl;
    __syncthreads();
    if (tid == 0) {
        int run = 0;
#pragma unroll
        for (int k = 0; k < 8; ++k) { int t = wsum[k]; wsum[k] = run; run += t; }
        sbase = (int)atomicAdd(&g_ctr, (unsigned)run);
    }
    __syncthreads();

    int o = sbase + wsum[wid] + (incl - cnt);        // exclusive offset
    const int r0 = gi * 4;
    if (c0) g_rows[o++] = r0;
    if (c1) g_rows[o++] = r0 + 1;
    if (c2) g_rows[o++] = r0 + 2;
    if (c3) g_rows[o++] = r0 + 3;
}

// ---------------------------------------------------------------------------
// Kernel 1: per-feature partial sum / sumsq over ONLY the masked rows
// (~64 MB instead of 128 MB). Row indices come from the dense list, so
// there is no inline mask test: 8 broadcast index loads (L2 hits) then 8
// independent LDG.128 gathers at 1 KB granularity (DRAM-efficient, MLP=8).
// thread = (float4 column f4 = tid&63, row-slot sub = tid>>6).
// Epilogue: smem reduce + coalesced plain partial stores (no atomics).
// ---------------------------------------------------------------------------
__global__ void __launch_bounds__(STATS_THREADS)
stats_kernel(const float* __restrict__ x) {
    const int tid = threadIdx.x;
    const int f4  = tid & 63;
    const int sub = tid >> 6;
    const int n   = (int)g_ctr;          // final after compact (stream order)

    const float4* __restrict__ x4 = (const float4*)x;

    float4 acc  = make_float4(0.f, 0.f, 0.f, 0.f);
    float4 acc2 = make_float4(0.f, 0.f, 0.f, 0.f);

#pragma unroll 1
    for (int base = blockIdx.x * 32; base < n; base += STATS_BLOCKS * 32) {
        int   row[8];
        float w[8];
#pragma unroll
        for (int u = 0; u < 8; ++u) {
            const int ridx = base + u * 4 + sub;
            const bool val = ridx < n;
            row[u] = val ? g_rows[ridx] : 0;   // broadcast L2 hit
            w[u]   = val ? 1.0f : 0.0f;
        }
        float4 v[8];
#pragma unroll
        for (int u = 0; u < 8; ++u)
            v[u] = __ldcg(&x4[(size_t)row[u] * F4 + f4]);  // fill L2 for apply
#pragma unroll
        for (int u = 0; u < 8; ++u) {
            const float wx = w[u];
            acc.x  = fmaf(v[u].x, wx, acc.x);
            acc.y  = fmaf(v[u].y, wx, acc.y);
            acc.z  = fmaf(v[u].z, wx, acc.z);
            acc.w  = fmaf(v[u].w, wx, acc.w);
            acc2.x = fmaf(v[u].x * wx, v[u].x, acc2.x);
            acc2.y = fmaf(v[u].y * wx, v[u].y, acc2.y);
            acc2.z = fmaf(v[u].z * wx, v[u].z, acc2.z);
            acc2.w = fmaf(v[u].w * wx, v[u].w, acc2.w);
        }
    }

    // ---- intra-block reduction across the 4 row-slots ----
    __shared__ float4 s_sum[256];
    __shared__ float4 s_sq[256];
    s_sum[tid] = acc;
    s_sq[tid]  = acc2;
    __syncthreads();

    if (sub == 0) {
#pragma unroll
        for (int k = 1; k < 4; k++) {
            float4 a = s_sum[tid + 64 * k];
            float4 b = s_sq[tid + 64 * k];
            acc.x += a.x; acc.y += a.y; acc.z += a.z; acc.w += a.w;
            acc2.x += b.x; acc2.y += b.y; acc2.z += b.z; acc2.w += b.w;
        }
        s_sum[f4] = acc;
        s_sq[f4]  = acc2;
    }
    __syncthreads();

    const float* rs = (const float*)s_sum;
    const float* rq = (const float*)s_sq;
    const size_t o = (size_t)blockIdx.x * F + tid;
    g_psum[o] = rs[tid];
    g_psq[o]  = rq[tid];
}

// ---------------------------------------------------------------------------
// Kernel 2: parallel reduce + finalize. 8 blocks x 256 threads; block b owns
// features [b*32, b*32+32). Count comes directly from g_ctr.
// ---------------------------------------------------------------------------
__global__ void __launch_bounds__(256)
reduce_finalize_kernel(const float* __restrict__ gamma,
                       const float* __restrict__ beta) {
    const int tid = threadIdx.x;
    const int fl  = tid & 31;
    const int j   = tid >> 5;                  // 0..7
    const int f   = blockIdx.x * 32 + fl;

    float sum = 0.f, sq = 0.f;
#pragma unroll 1
    for (int b = j * 128; b < (j + 1) * 128; b += 8) {
        float a0[8], a1[8];
#pragma unroll
        for (int u = 0; u < 8; ++u) {
            a0[u] = g_psum[(size_t)(b + u) * F + f];
            a1[u] = g_psq [(size_t)(b + u) * F + f];
        }
#pragma unroll
        for (int u = 0; u < 8; ++u) { sum += a0[u]; sq += a1[u]; }
    }

    __shared__ float s_sum[256];
    __shared__ float s_sq[256];
    s_sum[tid] = sum;
    s_sq[tid]  = sq;
    __syncthreads();

    if (j == 0) {
#pragma unroll
        for (int k = 1; k < 8; ++k) {
            sum += s_sum[fl + 32 * k];
            sq  += s_sq[fl + 32 * k];
        }
        const float cnt  = (float)g_ctr;
        const float mean = sum / cnt;
        const float var  = sq / cnt - mean * mean;
        const float s    = rsqrtf(var + EPS) * gamma[f];
        g_scale[f] = s;
        g_bias[f]  = beta[f] - mean * s;
    }
}

// ---------------------------------------------------------------------------
// Kernel 3: apply, reversed block order (consume the L2-resident tail of x
// first). Mask branch warp-uniform; streaming hints. Also resets g_ctr for
// the next call/replay (nothing reads it after reduce).
// ---------------------------------------------------------------------------
__global__ void __launch_bounds__(256) apply_kernel(const float* __restrict__ x,
                                                    const int*   __restrict__ mask,
                                                    float*       __restrict__ out) {
    if (blockIdx.x == 0 && threadIdx.x == 0) g_ctr = 0;   // reset for next call

    const unsigned bid = (unsigned)(APPLY_BLOCKS - 1) - blockIdx.x;  // reverse
    const size_t i = (size_t)bid * blockDim.x + threadIdx.x;         // float4 index
    const float4* __restrict__ x4 = (const float4*)x;
    float4* __restrict__ out4 = (float4*)out;

    const int row = (int)(i >> 6);       // 64 float4 per row
    const int f4  = (int)(i & 63);

    float4 v = __ldcs(&x4[i]);
    if (mask[row] > 0) {
        const float4* s4 = (const float4*)g_scale;
        const float4* b4 = (const float4*)g_bias;
        float4 s = s4[f4];
        float4 b = b4[f4];
        v.x = fmaf(v.x, s.x, b.x);
        v.y = fmaf(v.y, s.y, b.y);
        v.z = fmaf(v.z, s.z, b.z);
        v.w = fmaf(v.w, s.w, b.w);
    }
    __stcs(&out4[i], v);
}

// ---------------------------------------------------------------------------
extern "C" void kernel_launch(void* const* d_in, const int* in_sizes, int n_in,
                              void* d_out, int out_size) {
    const float* x     = (const float*)d_in[0];
    const int*   mask  = (const int*)d_in[1];
    const float* gamma = (const float*)d_in[2];
    const float* beta  = (const float*)d_in[3];
    float*       out   = (float*)d_out;

    compact_kernel<<<COMPACT_BLOCKS, 256>>>(mask);
    stats_kernel<<<STATS_BLOCKS, STATS_THREADS>>>(x);
    reduce_finalize_kernel<<<RED_BLOCKS, 256>>>(gamma, beta);
    apply_kernel<<<APPLY_BLOCKS, 256>>>(x, mask, out);
}

// round 10
// speedup vs baseline: 3.0381x; 1.0543x over previous
#include <cuda_runtime.h>

#define F 256
#define F4 (F / 4)                   // 64 float4 per row
#define TOTAL_ROWS (32 * 4096)       // B*T = 131072
#define STATS_BLOCKS 1024
#define ROWS_PER_BLOCK 128           // block territory
#define STATS_THREADS 256
#define RED_BLOCKS 8
#define APPLY_BLOCKS 32768
#define EPS 1e-5f

// Scratch (no cudaMalloc). Everything is fully overwritten before being
// read on every call -> deterministic, graph-replay safe, no init kernel,
// no carried state.
__device__ float g_psum[STATS_BLOCKS * F];
__device__ float g_psq [STATS_BLOCKS * F];
__device__ float g_pcnt[STATS_BLOCKS];
__device__ float g_scale[F];
__device__ float g_bias[F];

// ---------------------------------------------------------------------------
// Kernel 1: per-feature partial sum / sumsq over ONLY masked rows, with
// IN-BLOCK index compaction (no separate compact kernel, no global list).
// Block b owns rows [b*128, b*128+128). Warps 0-3 ballot-compact the masked
// row indices into smem (~30 cyc), then all 256 threads gather them in
// batches of 8 independent LDG.128 (1 KB granularity, MLP=8). __ldcg fills
// L2 so apply re-hits the resident tail. Epilogue: smem reduce + coalesced
// plain partial stores (no atomics — the R4/R5 killer).
// ---------------------------------------------------------------------------
__global__ void __launch_bounds__(STATS_THREADS)
stats_kernel(const float* __restrict__ x, const int* __restrict__ mask) {
    const int tid  = threadIdx.x;
    const int f4   = tid & 63;       // float4 column within row
    const int sub  = tid >> 6;       // row slot 0..3
    const int row0 = blockIdx.x * ROWS_PER_BLOCK;

    __shared__ int   s_rows[ROWS_PER_BLOCK];
    __shared__ int   s_wbase[5];

    // ---- local compaction: threads 0..127 test one row each ----
    if (tid < ROWS_PER_BLOCK) {
        const int  lane = tid & 31;
        const int  w    = tid >> 5;              // warp-slice 0..3
        const bool p    = mask[row0 + tid] > 0;
        const unsigned bal = __ballot_sync(0xffffffffu, p);
        if (lane == 0) s_wbase[w + 1] = __popc(bal);
        if (tid == 0)  s_wbase[0] = 0;
        __syncwarp();
        // cross-warp exclusive scan done redundantly by thread 0 after sync
        if (p) {
            // position within warp slice
            const int inwarp = __popc(bal & ((1u << lane) - 1u));
            // warp bases resolved after block sync below; store pair packed:
            // temporarily stash (w, inwarp, row) via direct scatter after scan.
            // To avoid a second sync phase, store into per-warp segment then
            // compact: simplest correct approach — two-phase with syncthreads.
            s_rows[w * 32 + inwarp] = row0 + tid;  // segmented, compacted per warp
        }
        if (lane == 0) s_wbase[w + 1] = __popc(bal);   // counts (redundant ok)
    }
    __syncthreads();

    // resolve segment bases and pack segments tight (few threads, cheap)
    __shared__ int s_list[ROWS_PER_BLOCK];
    __shared__ int s_cnt;
    if (tid == 0) {
        int run = 0;
#pragma unroll
        for (int k = 0; k < 4; ++k) { int c = s_wbase[k + 1]; s_wbase[k] = run; run += c; }
        s_cnt = run;
        s_wbase[4] = run;
    }
    __syncthreads();
    if (tid < ROWS_PER_BLOCK) {
        const int w = tid >> 5, lane = tid & 31;
        const int segc = s_wbase[w + 1] - s_wbase[w];   // count in this segment
        if (lane < segc) s_list[s_wbase[w] + lane] = s_rows[w * 32 + lane];
    }
    __syncthreads();

    const int cnt = s_cnt;
    const float4* __restrict__ x4 = (const float4*)x;

    float4 acc  = make_float4(0.f, 0.f, 0.f, 0.f);
    float4 acc2 = make_float4(0.f, 0.f, 0.f, 0.f);

    // gather masked rows: 32 rows per iteration (8 per row-slot), <=4 iters
#pragma unroll 1
    for (int base = 0; base < cnt; base += 32) {
        int   row[8];
        float w[8];
#pragma unroll
        for (int u = 0; u < 8; ++u) {
            const int k = base + u * 4 + sub;
            const bool val = k < cnt;
            row[u] = val ? s_list[k] : s_list[0];   // smem broadcast
            w[u]   = val ? 1.0f : 0.0f;
        }
        float4 v[8];
#pragma unroll
        for (int u = 0; u < 8; ++u)
            v[u] = __ldcg(&x4[(size_t)row[u] * F4 + f4]);   // fill L2 for apply
#pragma unroll
        for (int u = 0; u < 8; ++u) {
            const float wx = w[u];
            acc.x  = fmaf(v[u].x, wx, acc.x);
            acc.y  = fmaf(v[u].y, wx, acc.y);
            acc.z  = fmaf(v[u].z, wx, acc.z);
            acc.w  = fmaf(v[u].w, wx, acc.w);
            acc2.x = fmaf(v[u].x * wx, v[u].x, acc2.x);
            acc2.y = fmaf(v[u].y * wx, v[u].y, acc2.y);
            acc2.z = fmaf(v[u].z * wx, v[u].z, acc2.z);
            acc2.w = fmaf(v[u].w * wx, v[u].w, acc2.w);
        }
    }

    // ---- intra-block reduction across the 4 row-slots ----
    __shared__ float4 s_sum[256];
    __shared__ float4 s_sq[256];
    s_sum[tid] = acc;
    s_sq[tid]  = acc2;
    __syncthreads();

    if (sub == 0) {
#pragma unroll
        for (int k = 1; k < 4; k++) {
            float4 a = s_sum[tid + 64 * k];
            float4 b = s_sq[tid + 64 * k];
            acc.x += a.x; acc.y += a.y; acc.z += a.z; acc.w += a.w;
            acc2.x += b.x; acc2.y += b.y; acc2.z += b.z; acc2.w += b.w;
        }
        s_sum[f4] = acc;
        s_sq[f4]  = acc2;
    }
    __syncthreads();

    const float* rs = (const float*)s_sum;
    const float* rq = (const float*)s_sq;
    const size_t o = (size_t)blockIdx.x * F + tid;
    g_psum[o] = rs[tid];
    g_psq[o]  = rq[tid];
    if (tid == 0) g_pcnt[blockIdx.x] = (float)cnt;
}

// ---------------------------------------------------------------------------
// Kernel 2: parallel reduce + finalize. 8 blocks x 256 threads; block b owns
// features [b*32, b*32+32). Thread = (fl = tid&31, slice j = tid>>5 of 128
// stats-blocks). Count (4 KB) reduced redundantly per block.
// ---------------------------------------------------------------------------
__global__ void __launch_bounds__(256)
reduce_finalize_kernel(const float* __restrict__ gamma,
                       const float* __restrict__ beta) {
    const int tid = threadIdx.x;
    const int fl  = tid & 31;
    const int j   = tid >> 5;                  // 0..7
    const int f   = blockIdx.x * 32 + fl;

    float sum = 0.f, sq = 0.f;
#pragma unroll 1
    for (int b = j * 128; b < (j + 1) * 128; b += 8) {
        float a0[8], a1[8];
#pragma unroll
        for (int u = 0; u < 8; ++u) {
            a0[u] = g_psum[(size_t)(b + u) * F + f];
            a1[u] = g_psq [(size_t)(b + u) * F + f];
        }
#pragma unroll
        for (int u = 0; u < 8; ++u) { sum += a0[u]; sq += a1[u]; }
    }

    float c = g_pcnt[tid] + g_pcnt[tid + 256] + g_pcnt[tid + 512] + g_pcnt[tid + 768];
#pragma unroll
    for (int off = 16; off > 0; off >>= 1)
        c += __shfl_down_sync(0xffffffffu, c, off);

    __shared__ float s_sum[256];
    __shared__ float s_sq[256];
    __shared__ float s_cw[8];
    __shared__ float s_total;
    s_sum[tid] = sum;
    s_sq[tid]  = sq;
    if ((tid & 31) == 0) s_cw[tid >> 5] = c;
    __syncthreads();
    if (tid == 0) {
        float t = 0.f;
#pragma unroll
        for (int k = 0; k < 8; ++k) t += s_cw[k];
        s_total = t;
    }
    __syncthreads();

    if (j == 0) {
#pragma unroll
        for (int k = 1; k < 8; ++k) {
            sum += s_sum[fl + 32 * k];
            sq  += s_sq[fl + 32 * k];
        }
        const float cnt  = s_total;
        const float mean = sum / cnt;
        const float var  = sq / cnt - mean * mean;
        const float s    = rsqrtf(var + EPS) * gamma[f];
        g_scale[f] = s;
        g_bias[f]  = beta[f] - mean * s;
    }
}

// ---------------------------------------------------------------------------
// Kernel 3: apply, reversed block order (consume the L2-resident tail of the
// stats gather first). Mask branch warp-uniform; streaming hints.
// ---------------------------------------------------------------------------
__global__ void __launch_bounds__(256) apply_kernel(const float* __restrict__ x,
                                                    const int*   __restrict__ mask,
                                                    float*       __restrict__ out) {
    const unsigned bid = (unsigned)(APPLY_BLOCKS - 1) - blockIdx.x;  // reverse
    const size_t i = (size_t)bid * blockDim.x + threadIdx.x;         // float4 index
    const float4* __restrict__ x4 = (const float4*)x;
    float4* __restrict__ out4 = (float4*)out;

    const int row = (int)(i >> 6);       // 64 float4 per row
    const int f4  = (int)(i & 63);

    float4 v = __ldcs(&x4[i]);
    if (mask[row] > 0) {
        const float4* s4 = (const float4*)g_scale;
        const float4* b4 = (const float4*)g_bias;
        float4 s = s4[f4];
        float4 b = b4[f4];
        v.x = fmaf(v.x, s.x, b.x);
        v.y = fmaf(v.y, s.y, b.y);
        v.z = fmaf(v.z, s.z, b.z);
        v.w = fmaf(v.w, s.w, b.w);
    }
    __stcs(&out4[i], v);
}

// ---------------------------------------------------------------------------
extern "C" void kernel_launch(void* const* d_in, const int* in_sizes, int n_in,
                              void* d_out, int out_size) {
    const float* x     = (const float*)d_in[0];
    const int*   mask  = (const int*)d_in[1];
    const float* gamma = (const float*)d_in[2];
    const float* beta  = (const float*)d_in[3];
    float*       out   = (float*)d_out;

    stats_kernel<<<STATS_BLOCKS, STATS_THREADS>>>(x, mask);
    reduce_finalize_kernel<<<RED_BLOCKS, 256>>>(gamma, beta);
    apply_kernel<<<APPLY_BLOCKS, 256>>>(x, mask, out);
}